// round 4
// baseline (speedup 1.0000x reference)
#include <cuda_runtime.h>

#define LOG2E 1.4426950408889634f

// ---------------- device scratch (no allocations allowed) ----------------
static __device__ __align__(16) float g_WhPart[16][4096][32];  // K-split partials
static __device__ __align__(16) float g_Wh[4][4096][8];        // Wh per head
static __device__ float g_ssrc2[4][4096];                      // a1.Wh_i * log2e
static __device__ float g_sdst2[4][4096];                      // a2.Wh_j * log2e
static __device__ float g_smax_part[32][4];
static __device__ float g_sdmax2[4];
static __device__ float g_outpart[256][8];
static __device__ float g_scratch_emb[32768];
static __device__ float g_scratch8[8];

// ---------------- packed f32x2 helpers (Blackwell FFMA2) ----------------
__device__ __forceinline__ unsigned long long pack2(float x, float y) {
    unsigned long long r;
    asm("mov.b64 %0, {%1,%2};" : "=l"(r) : "f"(x), "f"(y));
    return r;
}
__device__ __forceinline__ void unpack2(unsigned long long v, float& x, float& y) {
    asm("mov.b64 {%0,%1}, %2;" : "=f"(x), "=f"(y) : "l"(v));
}
__device__ __forceinline__ unsigned long long fma2(unsigned long long a,
                                                   unsigned long long b,
                                                   unsigned long long c) {
    unsigned long long r;
    asm("fma.rn.f32x2 %0, %1, %2, %3;" : "=l"(r) : "l"(a), "l"(b), "l"(c));
    return r;
}
__device__ __forceinline__ float ex2f(float x) {
    float r;
    asm("ex2.approx.ftz.f32 %0, %1;" : "=f"(r) : "f"(x));
    return r;
}

// ---------------- Kernel 1: Wh = x @ W  (K-split x16, packed fp32) ------------
// grid (32 row-tiles, 16 K-chunks), 256 threads: thread = (row, col-half).
// 8 packed-f32x2 accumulators = 16 output cols. W tile read as broadcast LDS.128.
__global__ __launch_bounds__(256) void k_gemm(const float* __restrict__ x,
                                              const float* __restrict__ W) {
    __shared__ __align__(16) float sx[128][33];   // +1 pad: conflict-free column reads
    __shared__ __align__(16) float sw[32][32];

    const int tid = threadIdx.x;
    const int row = tid & 127;
    const int cg  = tid >> 7;          // column half: 0 -> cols 0-15, 1 -> 16-31
    const int r0 = blockIdx.x * 128;
    const int k0 = blockIdx.y * 256;

    unsigned long long acc[8];
#pragma unroll
    for (int i = 0; i < 8; i++) acc[i] = 0ull;

    for (int kt = 0; kt < 256; kt += 32) {
        // stage x[128][32]: 1024 float4 / 256 threads = 4 each
#pragma unroll
        for (int p = 0; p < 4; p++) {
            int idx = tid + p * 256;
            int r = idx >> 3, f = idx & 7;
            float4 v = *(const float4*)&x[(size_t)(r0 + r) * 4096 + k0 + kt + f * 4];
            sx[r][f * 4 + 0] = v.x;
            sx[r][f * 4 + 1] = v.y;
            sx[r][f * 4 + 2] = v.z;
            sx[r][f * 4 + 3] = v.w;
        }
        // stage W[32][32]  (col c -> head c>>3, out c&7): 4 each
#pragma unroll
        for (int p = 0; p < 4; p++) {
            int idx = tid + p * 256;
            int k = idx >> 5, c = idx & 31;
            sw[k][c] = W[(c >> 3) * 32768 + (k0 + kt + k) * 8 + (c & 7)];
        }
        __syncthreads();

#pragma unroll 8
        for (int k = 0; k < 32; k++) {
            float xv = sx[row][k];
            unsigned long long xp = pack2(xv, xv);
            const ulonglong2* wrow = (const ulonglong2*)&sw[k][cg * 16];
#pragma unroll
            for (int q = 0; q < 4; q++) {                 // 4x broadcast LDS.128
                ulonglong2 wv = wrow[q];
                acc[2 * q + 0] = fma2(xp, wv.x, acc[2 * q + 0]);
                acc[2 * q + 1] = fma2(xp, wv.y, acc[2 * q + 1]);
            }
        }
        __syncthreads();
    }

    float* dst = &g_WhPart[blockIdx.y][r0 + row][cg * 16];
#pragma unroll
    for (int c2 = 0; c2 < 8; c2++) {
        float lo, hi;
        unpack2(acc[c2], lo, hi);
        dst[2 * c2 + 0] = lo;
        dst[2 * c2 + 1] = hi;
    }
}

// ---------------- Kernel 2: reduce K-split, compute s_src/s_dst (log2 units) ----
// grid (32 n-tiles, 4 heads), 128 threads: one (h, n) per thread, float4 loads.
__global__ __launch_bounds__(128) void k_reduce_s(const float* __restrict__ a) {
    __shared__ float red[128];
    const int tid = threadIdx.x;
    const int n = blockIdx.x * 128 + tid;
    const int h = blockIdx.y;

    float4 v0 = make_float4(0.f, 0.f, 0.f, 0.f);
    float4 v1 = make_float4(0.f, 0.f, 0.f, 0.f);
#pragma unroll
    for (int ks = 0; ks < 16; ks++) {
        const float4* src = (const float4*)&g_WhPart[ks][n][h * 8];
        float4 a0 = src[0], a1 = src[1];
        v0.x += a0.x; v0.y += a0.y; v0.z += a0.z; v0.w += a0.w;
        v1.x += a1.x; v1.y += a1.y; v1.z += a1.z; v1.w += a1.w;
    }
    ((float4*)&g_Wh[h][n][0])[0] = v0;
    ((float4*)&g_Wh[h][n][0])[1] = v1;

    float s1 = v0.x * a[h*16+0] + v0.y * a[h*16+1] + v0.z * a[h*16+2] + v0.w * a[h*16+3]
             + v1.x * a[h*16+4] + v1.y * a[h*16+5] + v1.z * a[h*16+6] + v1.w * a[h*16+7];
    float s2 = v0.x * a[h*16+8] + v0.y * a[h*16+9] + v0.z * a[h*16+10] + v0.w * a[h*16+11]
             + v1.x * a[h*16+12] + v1.y * a[h*16+13] + v1.z * a[h*16+14] + v1.w * a[h*16+15];

    g_ssrc2[h][n] = s1 * LOG2E;
    float sd2 = s2 * LOG2E;
    g_sdst2[h][n] = sd2;

    red[tid] = sd2;
    __syncthreads();
    for (int s = 64; s > 0; s >>= 1) {
        if (tid < s) red[tid] = fmaxf(red[tid], red[tid + s]);
        __syncthreads();
    }
    if (tid == 0) g_smax_part[blockIdx.x][h] = red[0];
}

__global__ void k_reduce_max() {
    int t = threadIdx.x;
    if (t < 4) {
        float m = -3.4e38f;
        for (int b = 0; b < 32; b++) m = fmaxf(m, g_smax_part[b][t]);
        g_sdmax2[t] = m;
    }
}

// ---------------- Kernel 3: fused masked-softmax attention + epilogue ----------
// grid 256 (16 rows i per block), 512 threads = 16 warps.
// warp w: head = w&3, row-group = w>>2 (4 rows). Mask staged as float BIAS
// {0, -20000} folded into the exp argument (underflow -> exact 0).
__global__ __launch_bounds__(512, 2) void k_attn(const int* __restrict__ adj,
                                                 const float* __restrict__ w_lin,
                                                 float* __restrict__ dout,
                                                 int out_size) {
    __shared__ __align__(16) float sWh[4 * 128 * 12];   // stride 12: conflict-free LDS.128
    __shared__ float sadjb[16][128];                    // mask bias, conflict-free LDS.32
    __shared__ float ssd[4][128];
    __shared__ float sh_hp[4][16][8];
    __shared__ float sh_emb[16][8];
    __shared__ float sh_ls[16][8];

    const int tid = threadIdx.x;
    const int wid = tid >> 5;
    const int lane = tid & 31;
    const int h = wid & 3;
    const int rg = wid >> 2;          // rows rg*4 .. rg*4+3
    const int i0 = blockIdx.x * 16;

    const float sdm = g_sdmax2[h];
    float p[4], q[4];
#pragma unroll
    for (int ii = 0; ii < 4; ii++) {
        float ss = g_ssrc2[h][i0 + rg * 4 + ii];
        float t = ss + sdm;
        float M2 = fmaxf(t, 0.2f * t);       // >= every unmasked e (log2 units)
        p[ii] = ss - M2;
        q[ii] = 0.2f * ss - M2;
    }

    unsigned long long acc[4][4];
    float lsum[4];
#pragma unroll
    for (int ii = 0; ii < 4; ii++) {
        lsum[ii] = 0.0f;
#pragma unroll
        for (int c = 0; c < 4; c++) acc[ii][c] = 0ull;
    }

    for (int jt = 0; jt < 4096; jt += 128) {
        // stage Wh tile: 4 heads x 128 j x 2 halves = 1024 float4 -> 2 per thread
#pragma unroll
        for (int ps = 0; ps < 2; ps++) {
            int idx = tid + ps * 512;
            int hh = idx >> 8, jj = (idx >> 1) & 127, half = idx & 1;
            float4 v = *(const float4*)&g_Wh[hh][jt + jj][half * 4];
            *(float4*)&sWh[hh * 1536 + jj * 12 + half * 4] = v;
        }
        // stage mask bias: 16 x 128 = 2048 -> 4 per thread
#pragma unroll
        for (int ps = 0; ps < 4; ps++) {
            int idx = tid + ps * 512;
            int r = idx >> 7, c = idx & 127;
            sadjb[r][c] = (adj[(i0 + r) * 4096 + jt + c] > 0) ? 0.0f : -20000.0f;
        }
        // stage s_dst: 512 -> 1 per thread
        ssd[tid >> 7][tid & 127] = g_sdst2[tid >> 7][jt + (tid & 127)];
        __syncthreads();

        const float* b0 = sadjb[rg * 4 + 0];
        const float* b1 = sadjb[rg * 4 + 1];
        const float* b2 = sadjb[rg * 4 + 2];
        const float* b3 = sadjb[rg * 4 + 3];

#pragma unroll
        for (int js = 0; js < 128; js += 32) {
            int jl = js + lane;
            const float* wbase = &sWh[h * 1536 + jl * 12];
            ulonglong2 wa = *(const ulonglong2*)(wbase);      // cols 0-3
            ulonglong2 wb = *(const ulonglong2*)(wbase + 4);  // cols 4-7
            float sd = ssd[h][jl];
            float mb[4] = {b0[jl], b1[jl], b2[jl], b3[jl]};
#pragma unroll
            for (int ii = 0; ii < 4; ii++) {
                float a1 = p[ii] + sd;
                float a2 = fmaf(0.2f, sd, q[ii]);
                float arg = fmaxf(a1, a2) + mb[ii];   // lrelu(e)-M + mask bias
                float w = ex2f(arg);                  // masked -> underflow to 0
                lsum[ii] += w;
                unsigned long long wp2 = pack2(w, w);
                acc[ii][0] = fma2(wp2, wa.x, acc[ii][0]);
                acc[ii][1] = fma2(wp2, wa.y, acc[ii][1]);
                acc[ii][2] = fma2(wp2, wb.x, acc[ii][2]);
                acc[ii][3] = fma2(wp2, wb.y, acc[ii][3]);
            }
        }
        __syncthreads();
    }

    // warp-reduce 8 accumulators + denom per row, normalize
#pragma unroll
    for (int ii = 0; ii < 4; ii++) {
        float fa[8];
        unpack2(acc[ii][0], fa[0], fa[1]);
        unpack2(acc[ii][1], fa[2], fa[3]);
        unpack2(acc[ii][2], fa[4], fa[5]);
        unpack2(acc[ii][3], fa[6], fa[7]);
        float l = lsum[ii];
#pragma unroll
        for (int s = 16; s > 0; s >>= 1) {
            l += __shfl_xor_sync(0xffffffffu, l, s);
#pragma unroll
            for (int c = 0; c < 8; c++) fa[c] += __shfl_xor_sync(0xffffffffu, fa[c], s);
        }
        if (lane == 0) {
            float inv = 1.0f / l;
#pragma unroll
            for (int c = 0; c < 8; c++) sh_hp[h][rg * 4 + ii][c] = fa[c] * inv;
        }
    }
    __syncthreads();

    float* oemb = (out_size >= 32776) ? (dout + (out_size - 32768))
                : ((out_size == 32768) ? dout : g_scratch_emb);

    if (tid < 128) {
        int ii = tid >> 3, c = tid & 7;
        float e = 0.25f * (sh_hp[0][ii][c] + sh_hp[1][ii][c] +
                           sh_hp[2][ii][c] + sh_hp[3][ii][c]);
        sh_emb[ii][c] = e;
        oemb[(i0 + ii) * 8 + c] = e;
    }
    __syncthreads();

    if (tid < 16) {   // log_softmax per row
        int ii = tid;
        float m = sh_emb[ii][0];
#pragma unroll
        for (int c = 1; c < 8; c++) m = fmaxf(m, sh_emb[ii][c]);
        float sum = 0.0f;
#pragma unroll
        for (int c = 0; c < 8; c++) sum += __expf(sh_emb[ii][c] - m);
        float lse = m + __logf(sum);
#pragma unroll
        for (int c = 0; c < 8; c++) sh_ls[ii][c] = sh_emb[ii][c] - lse;
    }
    __syncthreads();

    if (tid < 8) {   // partial of out[c] = sum_n ls[n][c] * w_lin[n]
        int c = tid;
        float pacc = 0.0f;
#pragma unroll
        for (int ii = 0; ii < 16; ii++) pacc += sh_ls[ii][c] * w_lin[i0 + ii];
        g_outpart[blockIdx.x][c] = pacc;
    }
}

// ---------------- Kernel 4: deterministic final reduction -> out[1,8] ----------
__global__ void k_final(const float* __restrict__ b_lin,
                        float* __restrict__ dout, int out_size) {
    __shared__ float sh[32][8];
    int c = threadIdx.x & 7, g = threadIdx.x >> 3;   // 256 threads
    float s = 0.0f;
    for (int b = g; b < 256; b += 32) s += g_outpart[b][c];
    sh[g][c] = s;
    __syncthreads();
    if (threadIdx.x < 8) {
        float t = b_lin[0];
        for (int g2 = 0; g2 < 32; g2++) t += sh[g2][threadIdx.x];
        float* oscal = (out_size >= 32776) ? dout
                     : ((out_size == 8) ? dout : g_scratch8);
        oscal[threadIdx.x] = t;
    }
}

// ---------------- launch ----------------
extern "C" void kernel_launch(void* const* d_in, const int* in_sizes, int n_in,
                              void* d_out, int out_size) {
    const float* x     = (const float*)d_in[0];
    const int*   adj   = (const int*)d_in[1];
    const float* W     = (const float*)d_in[2];
    const float* a     = (const float*)d_in[3];
    const float* w_lin = (const float*)d_in[4];
    const float* b_lin = (const float*)d_in[5];
    float* dout = (float*)d_out;

    k_gemm<<<dim3(32, 16), 256>>>(x, W);
    k_reduce_s<<<dim3(32, 4), 128>>>(a);
    k_reduce_max<<<1, 32>>>();
    k_attn<<<256, 512>>>(adj, w_lin, dout, out_size);
    k_final<<<1, 256>>>(b_lin, dout, out_size);
}

// round 6
// speedup vs baseline: 1.2574x; 1.2574x over previous
#include <cuda_runtime.h>

#define LOG2E 1.4426950408889634f

// ---------------- device scratch (no allocations allowed) ----------------
static __device__ __align__(16) float g_WhPart[32][4096][32];  // K-split partials
static __device__ __align__(16) float g_Wh[4][4096][8];        // Wh per head
static __device__ float g_ssrc2[4][4096];                      // a1.Wh_i * log2e
static __device__ float g_sdst2[4][4096];                      // a2.Wh_j * log2e
static __device__ float g_smax_part[32][4];
static __device__ float g_sdmax2[4];
static __device__ float g_outpart[256][8];
static __device__ float g_scratch_emb[32768];
static __device__ float g_scratch8[8];

// ---------------- packed f32x2 helpers (Blackwell FFMA2) ----------------
__device__ __forceinline__ unsigned long long pack2(float x, float y) {
    unsigned long long r;
    asm("mov.b64 %0, {%1,%2};" : "=l"(r) : "f"(x), "f"(y));
    return r;
}
__device__ __forceinline__ void unpack2(unsigned long long v, float& x, float& y) {
    asm("mov.b64 {%0,%1}, %2;" : "=f"(x), "=f"(y) : "l"(v));
}
__device__ __forceinline__ unsigned long long fma2(unsigned long long a,
                                                   unsigned long long b,
                                                   unsigned long long c) {
    unsigned long long r;
    asm("fma.rn.f32x2 %0, %1, %2, %3;" : "=l"(r) : "l"(a), "l"(b), "l"(c));
    return r;
}
__device__ __forceinline__ float ex2f(float x) {
    float r;
    asm("ex2.approx.ftz.f32 %0, %1;" : "=f"(r) : "f"(x));
    return r;
}

// ---------------- Kernel 1: Wh = x @ W  (K-split x32, packed fp32) ------------
// grid (32 row-tiles, 32 K-chunks), 256 threads: thread = (row, col-half).
// 8 packed-f32x2 accumulators = 16 output cols. W tile read as broadcast LDS.128.
__global__ __launch_bounds__(256) void k_gemm(const float* __restrict__ x,
                                              const float* __restrict__ W) {
    __shared__ __align__(16) float sx[128][33];   // +1 pad: conflict-free column reads
    __shared__ __align__(16) float sw[32][32];

    const int tid = threadIdx.x;
    const int row = tid & 127;
    const int cg  = tid >> 7;          // column half: 0 -> cols 0-15, 1 -> 16-31
    const int r0 = blockIdx.x * 128;
    const int k0 = blockIdx.y * 128;

    unsigned long long acc[8];
#pragma unroll
    for (int i = 0; i < 8; i++) acc[i] = 0ull;

#pragma unroll
    for (int kt = 0; kt < 128; kt += 32) {
        // stage x[128][32]: 1024 float4 / 256 threads = 4 each
#pragma unroll
        for (int p = 0; p < 4; p++) {
            int idx = tid + p * 256;
            int r = idx >> 3, f = idx & 7;
            float4 v = *(const float4*)&x[(size_t)(r0 + r) * 4096 + k0 + kt + f * 4];
            sx[r][f * 4 + 0] = v.x;
            sx[r][f * 4 + 1] = v.y;
            sx[r][f * 4 + 2] = v.z;
            sx[r][f * 4 + 3] = v.w;
        }
        // stage W[32][32]  (col c -> head c>>3, out c&7): 4 each
#pragma unroll
        for (int p = 0; p < 4; p++) {
            int idx = tid + p * 256;
            int k = idx >> 5, c = idx & 31;
            sw[k][c] = W[(c >> 3) * 32768 + (k0 + kt + k) * 8 + (c & 7)];
        }
        __syncthreads();

#pragma unroll 8
        for (int k = 0; k < 32; k++) {
            float xv = sx[row][k];
            unsigned long long xp = pack2(xv, xv);
            const ulonglong2* wrow = (const ulonglong2*)&sw[k][cg * 16];
#pragma unroll
            for (int q = 0; q < 4; q++) {                 // 4x broadcast LDS.128
                ulonglong2 wv = wrow[q];
                acc[2 * q + 0] = fma2(xp, wv.x, acc[2 * q + 0]);
                acc[2 * q + 1] = fma2(xp, wv.y, acc[2 * q + 1]);
            }
        }
        __syncthreads();
    }

    float* dst = &g_WhPart[blockIdx.y][r0 + row][cg * 16];
#pragma unroll
    for (int c2 = 0; c2 < 8; c2++) {
        float lo, hi;
        unpack2(acc[c2], lo, hi);
        dst[2 * c2 + 0] = lo;
        dst[2 * c2 + 1] = hi;
    }
}

// ---------------- Kernel 2: reduce K-split, compute s_src/s_dst (log2 units) ----
// grid (32 n-tiles, 4 heads), 128 threads: one (h, n) per thread, float4 loads.
__global__ __launch_bounds__(128) void k_reduce_s(const float* __restrict__ a) {
    __shared__ float red[128];
    const int tid = threadIdx.x;
    const int n = blockIdx.x * 128 + tid;
    const int h = blockIdx.y;

    float4 v0 = make_float4(0.f, 0.f, 0.f, 0.f);
    float4 v1 = make_float4(0.f, 0.f, 0.f, 0.f);
#pragma unroll
    for (int ks = 0; ks < 32; ks++) {
        const float4* src = (const float4*)&g_WhPart[ks][n][h * 8];
        float4 a0 = src[0], a1 = src[1];
        v0.x += a0.x; v0.y += a0.y; v0.z += a0.z; v0.w += a0.w;
        v1.x += a1.x; v1.y += a1.y; v1.z += a1.z; v1.w += a1.w;
    }
    ((float4*)&g_Wh[h][n][0])[0] = v0;
    ((float4*)&g_Wh[h][n][0])[1] = v1;

    float s1 = v0.x * a[h*16+0] + v0.y * a[h*16+1] + v0.z * a[h*16+2] + v0.w * a[h*16+3]
             + v1.x * a[h*16+4] + v1.y * a[h*16+5] + v1.z * a[h*16+6] + v1.w * a[h*16+7];
    float s2 = v0.x * a[h*16+8] + v0.y * a[h*16+9] + v0.z * a[h*16+10] + v0.w * a[h*16+11]
             + v1.x * a[h*16+12] + v1.y * a[h*16+13] + v1.z * a[h*16+14] + v1.w * a[h*16+15];

    g_ssrc2[h][n] = s1 * LOG2E;
    float sd2 = s2 * LOG2E;
    g_sdst2[h][n] = sd2;

    red[tid] = sd2;
    __syncthreads();
    for (int s = 64; s > 0; s >>= 1) {
        if (tid < s) red[tid] = fmaxf(red[tid], red[tid + s]);
        __syncthreads();
    }
    if (tid == 0) g_smax_part[blockIdx.x][h] = red[0];
}

__global__ void k_reduce_max() {
    int t = threadIdx.x;
    if (t < 4) {
        float m = -3.4e38f;
        for (int b = 0; b < 32; b++) m = fmaxf(m, g_smax_part[b][t]);
        g_sdmax2[t] = m;
    }
}

// ---------------- Kernel 3: fused masked-softmax attention + epilogue ----------
// grid 256 (16 rows i per block), 512 threads = 16 warps.
// warp w: head = w&3, row-group = w>>2 (4 rows; rg in 0..3 -> all 16 rows covered).
// Mask staged as float BIAS {0, -20000} folded into the exp argument
// (underflow -> exact 0; no select/compare in the hot loop). 256-j tiles.
__global__ __launch_bounds__(512, 2) void k_attn(const int* __restrict__ adj,
                                                 const float* __restrict__ w_lin,
                                                 float* __restrict__ dout,
                                                 int out_size) {
    __shared__ __align__(16) float sWh[4 * 256 * 12];   // 48KB, stride 12: conflict-free LDS.128
    __shared__ float sadjb[16][256];                    // 16KB mask bias, LDS.32 conflict-free
    __shared__ float ssd[4][256];                       // 4KB
    __shared__ float sh_hp[4][16][8];
    __shared__ float sh_emb[16][8];
    __shared__ float sh_ls[16][8];

    const int tid = threadIdx.x;
    const int wid = tid >> 5;
    const int lane = tid & 31;
    const int h = wid & 3;
    const int rg = wid >> 2;          // 0..3 -> rows rg*4 .. rg*4+3
    const int i0 = blockIdx.x * 16;

    const float sdm = g_sdmax2[h];
    float p[4], q[4];
#pragma unroll
    for (int ii = 0; ii < 4; ii++) {
        float ss = g_ssrc2[h][i0 + rg * 4 + ii];
        float t = ss + sdm;
        float M2 = fmaxf(t, 0.2f * t);       // >= every unmasked e (log2 units)
        p[ii] = ss - M2;
        q[ii] = 0.2f * ss - M2;
    }

    unsigned long long acc[4][4];
    float lsum[4];
#pragma unroll
    for (int ii = 0; ii < 4; ii++) {
        lsum[ii] = 0.0f;
#pragma unroll
        for (int c = 0; c < 4; c++) acc[ii][c] = 0ull;
    }

    for (int jt = 0; jt < 4096; jt += 256) {
        // stage Wh tile: 4 heads x 256 j x 2 halves = 2048 float4 -> 4 per thread
#pragma unroll
        for (int ps = 0; ps < 4; ps++) {
            int idx = tid + ps * 512;
            int hh = idx >> 9, jj = (idx >> 1) & 255, half = idx & 1;
            float4 v = *(const float4*)&g_Wh[hh][jt + jj][half * 4];
            *(float4*)&sWh[hh * 3072 + jj * 12 + half * 4] = v;
        }
        // stage mask bias: 16 rows x 256 cols = 1024 int4 -> 2 per thread
#pragma unroll
        for (int ps = 0; ps < 2; ps++) {
            int idx = tid + ps * 512;
            int r = idx >> 6, c4 = (idx & 63) * 4;
            int4 v = *(const int4*)&adj[(size_t)(i0 + r) * 4096 + jt + c4];
            sadjb[r][c4 + 0] = (v.x > 0) ? 0.0f : -20000.0f;
            sadjb[r][c4 + 1] = (v.y > 0) ? 0.0f : -20000.0f;
            sadjb[r][c4 + 2] = (v.z > 0) ? 0.0f : -20000.0f;
            sadjb[r][c4 + 3] = (v.w > 0) ? 0.0f : -20000.0f;
        }
        // stage s_dst: 1024 -> 2 per thread
#pragma unroll
        for (int ps = 0; ps < 2; ps++) {
            int idx = tid + ps * 512;
            ssd[idx >> 8][idx & 255] = g_sdst2[idx >> 8][jt + (idx & 255)];
        }
        __syncthreads();

        const float* b0 = sadjb[rg * 4 + 0];
        const float* b1 = sadjb[rg * 4 + 1];
        const float* b2 = sadjb[rg * 4 + 2];
        const float* b3 = sadjb[rg * 4 + 3];

#pragma unroll 4
        for (int js = 0; js < 256; js += 32) {
            int jl = js + lane;
            const float* wbase = &sWh[h * 3072 + jl * 12];
            ulonglong2 wa = *(const ulonglong2*)(wbase);      // cols 0-3
            ulonglong2 wb = *(const ulonglong2*)(wbase + 4);  // cols 4-7
            float sd = ssd[h][jl];
            float mb[4] = {b0[jl], b1[jl], b2[jl], b3[jl]};
#pragma unroll
            for (int ii = 0; ii < 4; ii++) {
                float a1 = p[ii] + sd;
                float a2 = fmaf(0.2f, sd, q[ii]);
                float arg = fmaxf(a1, a2) + mb[ii];   // lrelu(e)-M + mask bias
                float w = ex2f(arg);                  // masked -> underflow to 0
                lsum[ii] += w;
                unsigned long long wp2 = pack2(w, w);
                acc[ii][0] = fma2(wp2, wa.x, acc[ii][0]);
                acc[ii][1] = fma2(wp2, wa.y, acc[ii][1]);
                acc[ii][2] = fma2(wp2, wb.x, acc[ii][2]);
                acc[ii][3] = fma2(wp2, wb.y, acc[ii][3]);
            }
        }
        __syncthreads();
    }

    // warp-reduce 8 accumulators + denom per row, normalize
#pragma unroll
    for (int ii = 0; ii < 4; ii++) {
        float fa[8];
        unpack2(acc[ii][0], fa[0], fa[1]);
        unpack2(acc[ii][1], fa[2], fa[3]);
        unpack2(acc[ii][2], fa[4], fa[5]);
        unpack2(acc[ii][3], fa[6], fa[7]);
        float l = lsum[ii];
#pragma unroll
        for (int s = 16; s > 0; s >>= 1) {
            l += __shfl_xor_sync(0xffffffffu, l, s);
#pragma unroll
            for (int c = 0; c < 8; c++) fa[c] += __shfl_xor_sync(0xffffffffu, fa[c], s);
        }
        if (lane == 0) {
            float inv = 1.0f / l;
#pragma unroll
            for (int c = 0; c < 8; c++) sh_hp[h][rg * 4 + ii][c] = fa[c] * inv;
        }
    }
    __syncthreads();

    float* oemb = (out_size >= 32776) ? (dout + (out_size - 32768))
                : ((out_size == 32768) ? dout : g_scratch_emb);

    if (tid < 128) {
        int ii = tid >> 3, c = tid & 7;
        float e = 0.25f * (sh_hp[0][ii][c] + sh_hp[1][ii][c] +
                           sh_hp[2][ii][c] + sh_hp[3][ii][c]);
        sh_emb[ii][c] = e;
        oemb[(i0 + ii) * 8 + c] = e;
    }
    __syncthreads();

    if (tid < 16) {   // log_softmax per row
        int ii = tid;
        float m = sh_emb[ii][0];
#pragma unroll
        for (int c = 1; c < 8; c++) m = fmaxf(m, sh_emb[ii][c]);
        float sum = 0.0f;
#pragma unroll
        for (int c = 0; c < 8; c++) sum += __expf(sh_emb[ii][c] - m);
        float lse = m + __logf(sum);
#pragma unroll
        for (int c = 0; c < 8; c++) sh_ls[ii][c] = sh_emb[ii][c] - lse;
    }
    __syncthreads();

    if (tid < 8) {   // partial of out[c] = sum_n ls[n][c] * w_lin[n]
        int c = tid;
        float pacc = 0.0f;
#pragma unroll
        for (int ii = 0; ii < 16; ii++) pacc += sh_ls[ii][c] * w_lin[i0 + ii];
        g_outpart[blockIdx.x][c] = pacc;
    }
}

// ---------------- Kernel 4: deterministic final reduction -> out[1,8] ----------
__global__ void k_final(const float* __restrict__ b_lin,
                        float* __restrict__ dout, int out_size) {
    __shared__ float sh[32][8];
    int c = threadIdx.x & 7, g = threadIdx.x >> 3;   // 256 threads
    float s = 0.0f;
    for (int b = g; b < 256; b += 32) s += g_outpart[b][c];
    sh[g][c] = s;
    __syncthreads();
    if (threadIdx.x < 8) {
        float t = b_lin[0];
        for (int g2 = 0; g2 < 32; g2++) t += sh[g2][threadIdx.x];
        float* oscal = (out_size >= 32776) ? dout
                     : ((out_size == 8) ? dout : g_scratch8);
        oscal[threadIdx.x] = t;
    }
}

// ---------------- launch ----------------
extern "C" void kernel_launch(void* const* d_in, const int* in_sizes, int n_in,
                              void* d_out, int out_size) {
    const float* x     = (const float*)d_in[0];
    const int*   adj   = (const int*)d_in[1];
    const float* W     = (const float*)d_in[2];
    const float* a     = (const float*)d_in[3];
    const float* w_lin = (const float*)d_in[4];
    const float* b_lin = (const float*)d_in[5];
    float* dout = (float*)d_out;

    k_gemm<<<dim3(32, 32), 256>>>(x, W);
    k_reduce_s<<<dim3(32, 4), 128>>>(a);
    k_reduce_max<<<1, 32>>>();
    k_attn<<<256, 512>>>(adj, w_lin, dout, out_size);
    k_final<<<1, 256>>>(b_lin, dout, out_size);
}